// round 7
// baseline (speedup 1.0000x reference)
#include <cuda_runtime.h>
#include <math.h>
#include <stdint.h>

#define NUM_LEVEL 16
#define N_POINTS  262144

struct LevelMeta {
    float    scale;
    uint32_t res;
    uint32_t offset;   // in float2 entries
    uint32_t mask;     // hsize-1 (hashed levels: hsize = 2^19)
    uint32_t hashed;
    uint32_t pad;
};

struct Meta {
    LevelMeta lv[NUM_LEVEL];
};

// One thread = TWO points x one level. Corner-interleaved so two independent
// gathers sit between dependent FMAs (MLP x2). min-blocks=4 -> up to 64 regs,
// preventing the ptxas 32-reg serialization seen in R4.
__global__ void __launch_bounds__(256, 4)
grid_encode_kernel(const float* __restrict__ pts,
                   const float2* __restrict__ emb,
                   float2* __restrict__ out,
                   Meta meta)
{
    const uint32_t tid = blockIdx.x * blockDim.x + threadIdx.x;

    const uint32_t pp = tid >> 4;          // point-pair index
    const uint32_t l  = tid & 15;          // level index
    const uint32_t n0 = pp * 2u;
    const uint32_t n1 = n0 + 1u;

    // 16 consecutive threads share each point: L1 broadcast
    const float ax = __ldg(pts + n0 * 3 + 0);
    const float ay = __ldg(pts + n0 * 3 + 1);
    const float az = __ldg(pts + n0 * 3 + 2);
    const float bx_ = __ldg(pts + n1 * 3 + 0);
    const float by_ = __ldg(pts + n1 * 3 + 1);
    const float bz_ = __ldg(pts + n1 * 3 + 2);

    const LevelMeta m = meta.lv[l];
    const float2* __restrict__ table = emb + m.offset;
    const uint32_t r      = m.res;
    const uint32_t r2     = r * r;
    const uint32_t mask   = m.mask;
    const bool     hashed = (m.hashed != 0u);

    // --- point A setup ---
    const float pxA = (ax + 1.0f) * 0.5f * m.scale;
    const float pyA = (ay + 1.0f) * 0.5f * m.scale;
    const float pzA = (az + 1.0f) * 0.5f * m.scale;
    const float gxA = floorf(pxA), gyA = floorf(pyA), gzA = floorf(pzA);
    const float fxA = pxA - gxA, fyA = pyA - gyA, fzA = pzA - gzA;
    const uint32_t ixA = (uint32_t)gxA, iyA = (uint32_t)gyA, izA = (uint32_t)gzA;
    const float wxA[2] = {1.0f - fxA, fxA};
    const float wyA[2] = {1.0f - fyA, fyA};
    const float wzA[2] = {1.0f - fzA, fzA};

    // --- point B setup ---
    const float pxB = (bx_ + 1.0f) * 0.5f * m.scale;
    const float pyB = (by_ + 1.0f) * 0.5f * m.scale;
    const float pzB = (bz_ + 1.0f) * 0.5f * m.scale;
    const float gxB = floorf(pxB), gyB = floorf(pyB), gzB = floorf(pzB);
    const float fxB = pxB - gxB, fyB = pyB - gyB, fzB = pzB - gzB;
    const uint32_t ixB = (uint32_t)gxB, iyB = (uint32_t)gyB, izB = (uint32_t)gzB;
    const float wxB[2] = {1.0f - fxB, fxB};
    const float wyB[2] = {1.0f - fyB, fyB};
    const float wzB[2] = {1.0f - fzB, fzB};

    float aAx = 0.0f, aAy = 0.0f, aBx = 0.0f, aBy = 0.0f;

    #pragma unroll
    for (int c = 0; c < 8; ++c) {
        const uint32_t bxc = (uint32_t)(c & 1);
        const uint32_t byc = (uint32_t)((c >> 1) & 1);
        const uint32_t bzc = (uint32_t)(c >> 2);

        // point A index (branchless)
        const uint32_t cxA = ixA + bxc, cyA = iyA + byc, czA = izA + bzc;
        const uint32_t hA = (cxA ^ (cyA * 2654435761u) ^ (czA * 805459861u)) & mask;
        const uint32_t dA = cxA + cyA * r + czA * r2;
        const uint32_t iA = hashed ? hA : dA;

        // point B index (branchless)
        const uint32_t cxB = ixB + bxc, cyB = iyB + byc, czB = izB + bzc;
        const uint32_t hB = (cxB ^ (cyB * 2654435761u) ^ (czB * 805459861u)) & mask;
        const uint32_t dB = cxB + cyB * r + czB * r2;
        const uint32_t iB = hashed ? hB : dB;

        // two independent gathers in flight before either consumer
        const float2 fA = __ldg(table + iA);
        const float2 fB = __ldg(table + iB);

        const float wA = wxA[bxc] * wyA[byc] * wzA[bzc];
        const float wB = wxB[bxc] * wyB[byc] * wzB[bzc];

        aAx = fmaf(wA, fA.x, aAx);
        aAy = fmaf(wA, fA.y, aAy);
        aBx = fmaf(wB, fB.x, aBx);
        aBy = fmaf(wB, fB.y, aBy);
    }

    out[n0 * (uint32_t)NUM_LEVEL + l] = make_float2(aAx, aAy);
    out[n1 * (uint32_t)NUM_LEVEL + l] = make_float2(aBx, aBy);
}

// Host-side meta, bit-matching the reference's double-precision math.
static void compute_meta(Meta& M)
{
    const double ls = 1.38191288;
    const double lg = log2(ls);
    uint32_t off = 0;
    for (int i = 0; i < NUM_LEVEL; ++i) {
        double s   = exp2((double)i * lg) * 16.0 - 1.0;
        int    res = (int)ceil(s) + 1;

        double   res_meta = ceil(16.0 * pow(ls, (double)i));
        double   p3 = res_meta * res_meta * res_meta;
        uint32_t p  = (p3 > 524288.0) ? 524288u : (uint32_t)p3;
        p = ((p + 7u) / 8u) * 8u;

        unsigned long long res3 =
            (unsigned long long)res * (unsigned long long)res * (unsigned long long)res;
        bool hashed = res3 > (unsigned long long)p;

        M.lv[i].scale  = (float)s;
        M.lv[i].res    = (uint32_t)res;
        M.lv[i].offset = off;
        M.lv[i].mask   = p - 1u;
        M.lv[i].hashed = hashed ? 1u : 0u;
        M.lv[i].pad    = 0;

        off += p;
    }
}

extern "C" void kernel_launch(void* const* d_in, const int* in_sizes, int n_in,
                              void* d_out, int out_size)
{
    const float*  pts = (const float*)d_in[0];   // [N_POINTS, 3]
    const float2* emb = (const float2*)d_in[1];  // [offs[-1], 2]
    float2*       out = (float2*)d_out;          // [N_POINTS, 16] float2

    Meta M;
    compute_meta(M);

    const uint32_t total   = (uint32_t)(N_POINTS / 2) * NUM_LEVEL;  // 2,097,152
    const uint32_t threads = 256;
    const uint32_t blocks  = total / threads;                       // exact

    grid_encode_kernel<<<blocks, threads>>>(pts, emb, out, M);
}

// round 8
// speedup vs baseline: 1.0412x; 1.0412x over previous
#include <cuda_runtime.h>
#include <math.h>
#include <stdint.h>

#define NUM_LEVEL 16
#define N_POINTS  262144

struct LevelMeta {
    float    scale;
    uint32_t res;
    uint32_t offset;   // in float2 entries
    uint32_t mask;     // hsize-1 (hashed levels: hsize = 2^19)
    uint32_t hashed;
    uint32_t pad;
};

struct Meta {
    LevelMeta lv[NUM_LEVEL];
};

__global__ void __launch_bounds__(256)
grid_encode_kernel(const float* __restrict__ pts,
                   const float2* __restrict__ emb,
                   float2* __restrict__ out,
                   Meta meta)
{
    const uint32_t tid = blockIdx.x * blockDim.x + threadIdx.x;
    // grid is exact: N_POINTS*16 / 256 blocks

    const uint32_t n = tid >> 4;     // point index
    const uint32_t l = tid & 15;     // level index

    // 16 consecutive threads share one point: L1 broadcast
    const float inx = __ldg(pts + n * 3 + 0);
    const float iny = __ldg(pts + n * 3 + 1);
    const float inz = __ldg(pts + n * 3 + 2);

    const LevelMeta m = meta.lv[l];

    const float px = (inx + 1.0f) * 0.5f * m.scale;
    const float py = (iny + 1.0f) * 0.5f * m.scale;
    const float pz = (inz + 1.0f) * 0.5f * m.scale;

    const float gx = floorf(px), gy = floorf(py), gz = floorf(pz);
    const float fx = px - gx,   fy = py - gy,   fz = pz - gz;

    const uint32_t ix = (uint32_t)gx;
    const uint32_t iy = (uint32_t)gy;
    const uint32_t iz = (uint32_t)gz;

    const float wx[2] = {1.0f - fx, fx};
    const float wy[2] = {1.0f - fy, fy};
    const float wz[2] = {1.0f - fz, fz};

    const float2* __restrict__ table = emb + m.offset;
    const uint32_t r      = m.res;
    const uint32_t r2     = r * r;
    const uint32_t mask   = m.mask;
    const bool     hashed = (m.hashed != 0u);

    float accx = 0.0f, accy = 0.0f;

    // Interleaved per-corner load+FMA; branchless index selection (one SEL).
    #pragma unroll
    for (int c = 0; c < 8; ++c) {
        const uint32_t bx = (uint32_t)(c & 1);
        const uint32_t by = (uint32_t)((c >> 1) & 1);
        const uint32_t bz = (uint32_t)(c >> 2);
        const uint32_t cx = ix + bx;
        const uint32_t cy = iy + by;
        const uint32_t cz = iz + bz;

        const uint32_t hidx = (cx ^ (cy * 2654435761u) ^ (cz * 805459861u)) & mask;
        const uint32_t didx = cx + cy * r + cz * r2;   // < hsize by construction
        const uint32_t idx  = hashed ? hidx : didx;    // SEL, no branch

        const float w = wx[bx] * wy[by] * wz[bz];
        const float2 f = __ldg(table + idx);
        accx = fmaf(w, f.x, accx);
        accy = fmaf(w, f.y, accy);
    }

    // Write-once output: streaming store (evict-first) so the 33.5MB output
    // stream doesn't displace embedding-table lines in L1/L2.
    __stcs(out + n * (uint32_t)NUM_LEVEL + l, make_float2(accx, accy));
}

// Host-side meta, bit-matching the reference's double-precision math.
static void compute_meta(Meta& M)
{
    const double ls = 1.38191288;
    const double lg = log2(ls);
    uint32_t off = 0;
    for (int i = 0; i < NUM_LEVEL; ++i) {
        double s   = exp2((double)i * lg) * 16.0 - 1.0;
        int    res = (int)ceil(s) + 1;

        double   res_meta = ceil(16.0 * pow(ls, (double)i));
        double   p3 = res_meta * res_meta * res_meta;
        uint32_t p  = (p3 > 524288.0) ? 524288u : (uint32_t)p3;
        p = ((p + 7u) / 8u) * 8u;

        unsigned long long res3 =
            (unsigned long long)res * (unsigned long long)res * (unsigned long long)res;
        bool hashed = res3 > (unsigned long long)p;

        M.lv[i].scale  = (float)s;
        M.lv[i].res    = (uint32_t)res;
        M.lv[i].offset = off;
        M.lv[i].mask   = p - 1u;
        M.lv[i].hashed = hashed ? 1u : 0u;
        M.lv[i].pad    = 0;

        off += p;
    }
}

extern "C" void kernel_launch(void* const* d_in, const int* in_sizes, int n_in,
                              void* d_out, int out_size)
{
    const float*  pts = (const float*)d_in[0];   // [N_POINTS, 3]
    const float2* emb = (const float2*)d_in[1];  // [offs[-1], 2]
    float2*       out = (float2*)d_out;          // [N_POINTS, 16] float2

    Meta M;
    compute_meta(M);

    const uint32_t total   = (uint32_t)N_POINTS * NUM_LEVEL;  // 4,194,304
    const uint32_t threads = 256;
    const uint32_t blocks  = total / threads;                 // exact

    grid_encode_kernel<<<blocks, threads>>>(pts, emb, out, M);
}